// round 5
// baseline (speedup 1.0000x reference)
#include <cuda_runtime.h>
#include <cuda_bf16.h>
#include <cstdint>

// out[b, p*64+m] = w[p,1]*S_b + (w[p,0]-w[p,1])*x[b,m],  S_b = sum_n x[b,n]
// (indices = 1 - eye(64) collapses the einsum to rank-1 + diagonal correction)
//
// HBM-bound: 64 MB read + 512 MB write, 6.16 TB/s achieved at R4.
// R5: two rows per warp — front-batched independent LDGs (MLP 2), interleaved
// shuffle-reduce chains, 8 stores per warp. 512-thread blocks, exact grid.

__global__ __launch_bounds__(512) void perm_closed_kernel(
    const float* __restrict__ x,
    const float* __restrict__ w,
    float* __restrict__ out)
{
    const int warp = (blockIdx.x * (blockDim.x >> 5)) + (threadIdx.x >> 5);
    const int lane = threadIdx.x & 31;
    const int row0 = warp * 2;           // this warp handles rows row0, row0+1

    // Front-batch both row loads (independent -> MLP 2).
    const float4* __restrict__ x4 = reinterpret_cast<const float4*>(x);
    const float4 xv0 = x4[(size_t)row0 * 16 + (lane & 15)];
    const float4 xv1 = x4[(size_t)(row0 + 1) * 16 + (lane & 15)];

    // Each 16-lane half holds a complete row: 4-step butterfly per row.
    // The two chains are independent -> SHFL latency overlaps.
    float S0 = (xv0.x + xv0.y) + (xv0.z + xv0.w);
    float S1 = (xv1.x + xv1.y) + (xv1.z + xv1.w);
    #pragma unroll
    for (int o = 8; o > 0; o >>= 1) {
        S0 += __shfl_xor_sync(0xffffffffu, S0, o);
        S1 += __shfl_xor_sync(0xffffffffu, S1, o);
    }

    // Output row = 128 float4. Lane l writes float4 f in {l, l+32, l+64, l+96}:
    //   p = f/16 = (lane>>4) + 2k,  m-block = f%16 = lane&15  (matches xv).
    float4* __restrict__ o4 = reinterpret_cast<float4*>(out) + (size_t)row0 * 128;
    const int p0 = lane >> 4;

    #pragma unroll
    for (int k = 0; k < 4; ++k) {
        const int p = p0 + 2 * k;
        const float w0 = __ldg(w + 2 * p);
        const float w1 = __ldg(w + 2 * p + 1);
        const float d = w0 - w1;         // diagonal correction (row-independent)
        const float a0 = w1 * S0;
        const float a1 = w1 * S1;
        float4 r0, r1;
        r0.x = fmaf(d, xv0.x, a0);  r1.x = fmaf(d, xv1.x, a1);
        r0.y = fmaf(d, xv0.y, a0);  r1.y = fmaf(d, xv1.y, a1);
        r0.z = fmaf(d, xv0.z, a0);  r1.z = fmaf(d, xv1.z, a1);
        r0.w = fmaf(d, xv0.w, a0);  r1.w = fmaf(d, xv1.w, a1);
        o4[lane + 32 * k]       = r0;
        o4[128 + lane + 32 * k] = r1;
    }
}

extern "C" void kernel_launch(void* const* d_in, const int* in_sizes, int n_in,
                              void* d_out, int out_size)
{
    const float* x = (const float*)d_in[0];   // (B, 64) fp32
    const float* w = (const float*)d_in[1];   // (8, 2)  fp32
    // d_in[2] = indices (64,64) int32 == 1 - eye: structure folded into the math.

    float* out = (float*)d_out;               // (B, 512) fp32
    const int B = in_sizes[0] / 64;           // 262144

    const int threads = 512;                  // 16 warps = 32 rows per block
    const int rows_per_block = (threads / 32) * 2;
    const int blocks = B / rows_per_block;    // 262144/32 = 8192, exact
    perm_closed_kernel<<<blocks, threads>>>(x, w, out);
}

// round 6
// speedup vs baseline: 1.0226x; 1.0226x over previous
#include <cuda_runtime.h>
#include <cuda_bf16.h>
#include <cstdint>

// out[b, p*64+m] = w[p,1]*S_b + (w[p,0]-w[p,1])*x[b,m],  S_b = sum_n x[b,n]
// (indices = 1 - eye(64) collapses the einsum to rank-1 + diagonal correction)
//
// HBM-bound: 64 MB read + 512 MB write. Best = R4 (88.4us kernel, 77.7% DRAM).
// R5 (2 rows/warp, MLP_p1=2) regressed per the cross-CTA L1tex-spread model.
// R6: R4 body (1 row/warp, MLP_p1=1) with 1024-thread blocks — half the CTA
// dispatch events, 2 CTAs/SM, exact 8192-block grid.

__global__ __launch_bounds__(1024) void perm_closed_kernel(
    const float* __restrict__ x,
    const float* __restrict__ w,
    float* __restrict__ out)
{
    const int row  = (blockIdx.x * (blockDim.x >> 5)) + (threadIdx.x >> 5);
    const int lane = threadIdx.x & 31;

    // Load this lane's float4 of the x row (16 float4 per row; 2 lanes share one,
    // coalesced 256B row fetch via L1 broadcast).
    const float4* __restrict__ x4 = reinterpret_cast<const float4*>(x) + (size_t)row * 16;
    const float4 xv = x4[lane & 15];

    // Each 16-lane half holds the complete row: 4-step butterfly within the half
    // gives the exact row sum.
    float S = (xv.x + xv.y) + (xv.z + xv.w);
    #pragma unroll
    for (int o = 8; o > 0; o >>= 1)
        S += __shfl_xor_sync(0xffffffffu, S, o);

    // Output row = 128 float4. Lane l writes float4 f in {l, l+32, l+64, l+96}.
    //   p = f/16 = (lane>>4) + 2k,  m-block = f%16 = lane&15  (matches xv).
    float4* __restrict__ o4 = reinterpret_cast<float4*>(out) + (size_t)row * 128;
    const int p0 = lane >> 4;

    #pragma unroll
    for (int k = 0; k < 4; ++k) {
        const int p = p0 + 2 * k;
        const float w0 = __ldg(w + 2 * p);
        const float w1 = __ldg(w + 2 * p + 1);
        const float a = w1 * S;          // coefficient for the row sum
        const float d = w0 - w1;         // diagonal correction
        float4 r;
        r.x = fmaf(d, xv.x, a);
        r.y = fmaf(d, xv.y, a);
        r.z = fmaf(d, xv.z, a);
        r.w = fmaf(d, xv.w, a);
        o4[lane + 32 * k] = r;
    }
}

extern "C" void kernel_launch(void* const* d_in, const int* in_sizes, int n_in,
                              void* d_out, int out_size)
{
    const float* x = (const float*)d_in[0];   // (B, 64) fp32
    const float* w = (const float*)d_in[1];   // (8, 2)  fp32
    // d_in[2] = indices (64,64) int32 == 1 - eye: structure folded into the math.

    float* out = (float*)d_out;               // (B, 512) fp32
    const int B = in_sizes[0] / 64;           // 262144

    const int threads = 1024;                 // 32 warps = 32 rows per block
    const int rows_per_block = threads / 32;
    const int blocks = B / rows_per_block;    // 262144/32 = 8192, exact
    perm_closed_kernel<<<blocks, threads>>>(x, w, out);
}